// round 13
// baseline (speedup 1.0000x reference)
#include <cuda_runtime.h>
#include <math.h>

#define NQb 12
#define SDIM 4096
#define TPB 256

typedef unsigned long long u64;

// ---------- packed f32x2 helpers ----------
__device__ __forceinline__ u64 pk2(float lo, float hi) {
    u64 r; asm("mov.b64 %0,{%1,%2};" : "=l"(r) : "f"(lo), "f"(hi)); return r;
}
__device__ __forceinline__ void unpk2(u64 v, float& lo, float& hi) {
    asm("mov.b64 {%0,%1},%2;" : "=f"(lo), "=f"(hi) : "l"(v));
}
__device__ __forceinline__ u64 f2mul(u64 a, u64 b) {
    u64 d; asm("mul.rn.f32x2 %0,%1,%2;" : "=l"(d) : "l"(a), "l"(b)); return d;
}
__device__ __forceinline__ u64 f2fma(u64 a, u64 b, u64 c) {
    u64 d; asm("fma.rn.f32x2 %0,%1,%2,%3;" : "=l"(d) : "l"(a), "l"(b), "l"(c)); return d;
}
__device__ __forceinline__ u64 cswap(u64 v) {
    float x, y; unpk2(v, x, y); return pk2(y, x);
}
__device__ __forceinline__ u64 cmulp(u64 a, float br, float bi) {   // a*(br+i bi)
    return f2fma(pk2(-bi, bi), cswap(a), f2mul(pk2(br, br), a));
}
__device__ __forceinline__ u64 cmul2(u64 a, u64 b) {
    float br, bi; unpk2(b, br, bi); return cmulp(a, br, bi);
}

// ---------- permutations & swizzle (constexpr so unrolled uses fold) ----------
__host__ __device__ constexpr int sigma12c(int x) {      // CNOT chain (verified)
    x ^= (x & 1) << 11;
    for (int p = 1; p <= 11; ++p) x ^= ((x >> p) & 1) << (p - 1);
    return x;
}
__host__ __device__ constexpr int sigpow(int x, int l) {
    for (int i = 0; i < l; ++i) x = sigma12c(x);
    return x;
}
__host__ __device__ constexpr int tau12c(int x) {        // sigma^{-1}
    for (int p = 11; p >= 1; --p) x ^= ((x >> p) & 1) << (p - 1);
    x ^= (x & 1) << 11;
    return x;
}
// g(1)=9, g(2)=3, g(4)=6, g(8)=4 — solves all 10 bank-conflict rank conditions
__host__ __device__ constexpr int gnib(int h) {
    return ((h & 1) ? 9 : 0) ^ ((h & 2) ? 3 : 0) ^ ((h & 4) ? 6 : 0) ^ ((h & 8) ? 4 : 0);
}
__host__ __device__ constexpr int beta2(int k) { return k ^ gnib((k >> 4) & 15); }

// 4 RY rotations via lifting (3 FMA per pair): reg bit bb <-> qubit (QHI-bb).
template <int QHI>
__device__ __forceinline__ void ry4_lift(u64 a[16], const float* __restrict__ tpL,
                                         const float* __restrict__ sryL) {
#pragma unroll
    for (int bb = 0; bb < 4; ++bb) {
        const float p = tpL[QHI - bb], q = sryL[QHI - bb];
        const u64 pp = pk2(p, p), qq = pk2(q, q);
        const int m = 1 << bb;
#pragma unroll
        for (int j0 = 0; j0 < 16; ++j0) {
            if (j0 & m) continue;        // compile-time pruned
            const int j1 = j0 | m;
            a[j0] = f2fma(pp, a[j1], a[j0]);
            a[j1] = f2fma(qq, a[j0], a[j1]);
            a[j0] = f2fma(pp, a[j1], a[j0]);
        }
    }
}

__global__ void __launch_bounds__(TPB, 4)
qsim_kernel(const float* __restrict__ xin, const float* __restrict__ params,
            const float* __restrict__ lin_w, const float* __restrict__ lin_b,
            float* __restrict__ out) {
    __shared__ u64 samp[SDIM];             // slot map evolves: S_L(k) = beta2(sigma^L(k))
    __shared__ u64 TLs[64], THs[64];       // layer-0 product tables
    __shared__ float2 sv[NQb][2];
    __shared__ float sry[60];              // sin(th) (lifting q), layers 1..5
    __shared__ float tP[60];               // -tan(th/2) (lifting p)
    __shared__ float tz[48];               // RZ angles, layers 1..4
    __shared__ float zoffC[4][16];         // RZ offsets for pass-C reg bits (qubits 3..0)
    __shared__ float Tsum[4];
    __shared__ float red8[8];

    const int t = threadIdx.x;             // 8 bits
    const int blk = blockIdx.x;
    const int lane = t & 31;

    // ---------- setup (identical to R11) ----------
    if (t < NQb) {
        const float h = tanhf(xin[blk * NQb + t]) * 1.5707963267948966f;
        const float ce = cosf(h), se = sinf(h);
        const float th = 0.5f * params[t];
        const float ct = cosf(th), st = sinf(th);
        const float a = ct * ce - st * se, b = st * ce + ct * se;
        const float t0 = params[NQb + t];
        const float c0 = cosf(0.5f * t0), s0 = sinf(0.5f * t0);
        sv[t][0] = make_float2(a * c0, -a * s0);
        sv[t][1] = make_float2(b * c0,  b * s0);
    }
    if (t < 60) {
        const int L = t / NQb, q = t - L * NQb;
        const float th = 0.5f * params[(L + 1) * 24 + q];
        sry[t] = sinf(th);
        tP[t] = -tanf(0.5f * th);
    }
    if (t < 48) {
        const int L = t / NQb, q = t - L * NQb;
        tz[t] = params[(L + 1) * 24 + NQb + q];
    }
    __syncthreads();

    if (t < 128) {
        const int n = t & 63;
        const int qb = (t < 64) ? 11 : 5;
        float2 a = sv[qb][n & 1];
#pragma unroll
        for (int p = 1; p < 6; ++p) {
            const float2 w = sv[qb - p][(n >> p) & 1];
            a = make_float2(a.x * w.x - a.y * w.y, a.x * w.y + a.y * w.x);
        }
        if (t < 64) TLs[n] = pk2(a.x, a.y); else THs[n] = pk2(a.x, a.y);
    }
    if (t < 64) {   // zoffC[L][j]: pass-C reg bit bb (k bit 8+bb) <-> qubit (3-bb)
        const int L = t >> 4, j = t & 15;
        const float* tzL = tz + L * NQb;
        float zo = 0.f;
#pragma unroll
        for (int bb = 0; bb < 4; ++bb)
            if ((j >> bb) & 1) zo += tzL[3 - bb];
        zoffC[L][j] = zo;
    }
    if (t >= 128 && t < 132) {
        const int L = t - 128; float s = 0.f;
#pragma unroll
        for (int q = 0; q < NQb; ++q) s += tz[L * NQb + q];
        Tsum[L] = s;
    }
    __syncthreads();

    // ---------- per-thread evolving index bases ----------
    int vA = t << 4;                        // pass-A t-part of k
    int vB = (t & 15) | ((t >> 4) << 8);    // pass-B t-part of k
    int vC = t;                             // pass-C t-part of k
    const int TAU_t = tau12c(t);            // measurement fold

    // ---------- layer-1 pass-A input: layer 0 + CNOT folded ----------
    const int S_t = sigma12c(t << 4);
    u64 amp[16];
#pragma unroll
    for (int j = 0; j < 16; ++j) {
        const int m = S_t ^ sigma12c(j);
        amp[j] = cmul2(TLs[m & 63], THs[(m >> 6) & 63]);
    }

    float accm = 0.f;

#pragma unroll
    for (int L = 0; L < 5; ++L) {          // physical layers 1..5 (FULLY UNROLLED)
        const float* tpL  = tP  + L * NQb;
        const float* sryL = sry + L * NQb;

        // pass A: k bits 0-3 on regs <-> qubits 11..8 (OWN slots — load==store set)
        const int aB = beta2(vA);
        if (L) {
#pragma unroll
            for (int j = 0; j < 16; ++j) amp[j] = samp[aB ^ beta2(sigpow(j, L))];
        }
        ry4_lift<11>(amp, tpL, sryL);
#pragma unroll
        for (int j = 0; j < 16; ++j) samp[aB ^ beta2(sigpow(j, L))] = amp[j];
        __syncthreads();

        // pass B: k bits 4-7 on regs <-> qubits 7..4 (OWN slots)
        const int bB = beta2(vB);
#pragma unroll
        for (int j = 0; j < 16; ++j) amp[j] = samp[bB ^ beta2(sigpow(j << 4, L))];
        ry4_lift<7>(amp, tpL, sryL);
#pragma unroll
        for (int j = 0; j < 16; ++j) samp[bB ^ beta2(sigpow(j << 4, L))] = amp[j];
        __syncthreads();

        // pass C: k bits 8-11 on regs <-> qubits 3..0 (OWN slots)
        const int cB = beta2(vC);
#pragma unroll
        for (int j = 0; j < 16; ++j) amp[j] = samp[cB ^ beta2(sigpow(j << 8, L))];
        ry4_lift<3>(amp, tpL, sryL);

        if (L < 4) {
            // fused RZ: phase(kC) = phb(t) + zoffC[L][j];  t bit b <-> qubit (11-b)
            const float* tzL = tz + L * NQb;
            float phb = -0.5f * Tsum[L];
            if (t & 1)   phb += tzL[11];
            if (t & 2)   phb += tzL[10];
            if (t & 4)   phb += tzL[9];
            if (t & 8)   phb += tzL[8];
            if (t & 16)  phb += tzL[7];
            if (t & 32)  phb += tzL[6];
            if (t & 64)  phb += tzL[5];
            if (t & 128) phb += tzL[4];
            const float* zoL = zoffC[L];
#pragma unroll
            for (int j = 0; j < 16; ++j) {
                float sp, cp;
                __sincosf(phb + zoL[j], &sp, &cp);
                amp[j] = cmulp(amp[j], cp, sp);
            }
            // store own slots — CNOT handled by slot-map relabel (no scatter!)
#pragma unroll
            for (int j = 0; j < 16; ++j) samp[cB ^ beta2(sigpow(j << 8, L))] = amp[j];
            __syncthreads();
            // relabel: S_{L+1} = S_L o sigma  ->  advance t-part indices
            vA = sigma12c(vA); vB = sigma12c(vB); vC = sigma12c(vC);
        } else {
            // last layer: RZ is |.|^2-invariant; fold final CNOT into weights
            u64 accp = 0ull;
#pragma unroll
            for (int j = 0; j < 16; ++j) {
                const int tm = TAU_t ^ tau12c(j << 8);
                const float w = (float)(NQb - 2 * __popc(tm));
                accp = f2fma(f2mul(amp[j], amp[j]), pk2(w, w), accp);
            }
            float wl, wh; unpk2(accp, wl, wh);
            accm = wl + wh;
        }
    }

    // ---------- reduction (8 warps) + head ----------
#pragma unroll
    for (int o = 16; o; o >>= 1) accm += __shfl_xor_sync(0xffffffffu, accm, o);
    if (lane == 0) red8[t >> 5] = accm;
    __syncthreads();
    if (t == 0) {
        float m = 0.f;
#pragma unroll
        for (int w = 0; w < 8; ++w) m += red8[w];
        const float z = (m / (float)NQb) * lin_w[0] + lin_b[0];
        out[blk] = 1.f / (1.f + expf(-z));
    }
}

extern "C" void kernel_launch(void* const* d_in, const int* in_sizes, int n_in,
                              void* d_out, int out_size) {
    const float* x      = (const float*)d_in[0];
    const float* params = (const float*)d_in[1];
    const float* lw     = (const float*)d_in[2];
    const float* lb     = (const float*)d_in[3];
    const int Bn = in_sizes[0] / NQb;      // 512
    qsim_kernel<<<Bn, TPB>>>(x, params, lw, lb, (float*)d_out);
}

// round 15
// speedup vs baseline: 2.8921x; 2.8921x over previous
#include <cuda_runtime.h>
#include <math.h>

#define NQb 12
#define SDIM 4096
#define TPB 256

typedef unsigned long long u64;

// ---------- packed f32x2 helpers ----------
__device__ __forceinline__ u64 pk2(float lo, float hi) {
    u64 r; asm("mov.b64 %0,{%1,%2};" : "=l"(r) : "f"(lo), "f"(hi)); return r;
}
__device__ __forceinline__ void unpk2(u64 v, float& lo, float& hi) {
    asm("mov.b64 {%0,%1},%2;" : "=f"(lo), "=f"(hi) : "l"(v));
}
__device__ __forceinline__ u64 f2mul(u64 a, u64 b) {
    u64 d; asm("mul.rn.f32x2 %0,%1,%2;" : "=l"(d) : "l"(a), "l"(b)); return d;
}
__device__ __forceinline__ u64 f2fma(u64 a, u64 b, u64 c) {
    u64 d; asm("fma.rn.f32x2 %0,%1,%2,%3;" : "=l"(d) : "l"(a), "l"(b), "l"(c)); return d;
}
__device__ __forceinline__ u64 cswap(u64 v) {
    float x, y; unpk2(v, x, y); return pk2(y, x);
}
__device__ __forceinline__ u64 cmulp(u64 a, float br, float bi) {   // a*(br+i bi)
    return f2fma(pk2(-bi, bi), cswap(a), f2mul(pk2(br, br), a));
}
__device__ __forceinline__ u64 cmul2(u64 a, u64 b) {
    float br, bi; unpk2(b, br, bi); return cmulp(a, br, bi);
}

// ---------- permutations & swizzle (constexpr) ----------
__host__ __device__ constexpr int sigma12c(int x) {      // CNOT chain (verified)
    x ^= (x & 1) << 11;
    for (int p = 1; p <= 11; ++p) x ^= ((x >> p) & 1) << (p - 1);
    return x;
}
__host__ __device__ constexpr int sigpow(int x, int l) {
    for (int i = 0; i < l; ++i) x = sigma12c(x);
    return x;
}
__host__ __device__ constexpr int tau12c(int x) {        // sigma^{-1}
    for (int p = 11; p >= 1; --p) x ^= ((x >> p) & 1) << (p - 1);
    x ^= (x & 1) << 11;
    return x;
}
// g(1)=9, g(2)=3, g(4)=6, g(8)=4 — solves all 10 bank-conflict rank conditions
__host__ __device__ constexpr int gnib(int h) {
    return ((h & 1) ? 9 : 0) ^ ((h & 2) ? 3 : 0) ^ ((h & 4) ? 6 : 0) ^ ((h & 8) ? 4 : 0);
}
__host__ __device__ constexpr int beta2(int k) { return k ^ gnib((k >> 4) & 15); }

// SCALAR compile-time constants (value-read of integral static constexpr: no odr-use)
template <int L, int j> struct OA { static constexpr int v = beta2(sigpow(j, L)); };
template <int L, int j> struct OB { static constexpr int v = beta2(sigpow(j << 4, L)); };
template <int L, int j> struct OC { static constexpr int v = beta2(sigpow(j << 8, L)); };
template <int j> struct SJc { static constexpr int v = sigma12c(j); };
template <int j> struct TJc { static constexpr int v = tau12c(j << 8); };

#define REP16(M) M(0) M(1) M(2) M(3) M(4) M(5) M(6) M(7) \
                 M(8) M(9) M(10) M(11) M(12) M(13) M(14) M(15)

// 4 RY rotations via lifting (3 FMA per pair): reg bit bb <-> qubit (QHI-bb).
template <int QHI>
__device__ __forceinline__ void ry4_lift(u64 a[16], const float* __restrict__ tpL,
                                         const float* __restrict__ sryL) {
#pragma unroll
    for (int bb = 0; bb < 4; ++bb) {
        const float p = tpL[QHI - bb], q = sryL[QHI - bb];
        const u64 pp = pk2(p, p), qq = pk2(q, q);
        const int m = 1 << bb;
#pragma unroll
        for (int j0 = 0; j0 < 16; ++j0) {
            if (j0 & m) continue;        // compile-time pruned
            const int j1 = j0 | m;
            a[j0] = f2fma(pp, a[j1], a[j0]);
            a[j1] = f2fma(qq, a[j0], a[j1]);
            a[j0] = f2fma(pp, a[j1], a[j0]);
        }
    }
}

// one circuit layer; L template param -> every smem offset is an immediate
template <int L>
__device__ __forceinline__ void layer_body(
    u64 amp[16], u64* __restrict__ samp,
    int aB, int bB, int cB,
    const float* __restrict__ tP, const float* __restrict__ sry,
    const float* __restrict__ tz, const float (* __restrict__ zoffC)[16],
    const float* __restrict__ Tsum, int t, int TAU_t, float& accm) {

    const float* tpL  = tP  + L * NQb;
    const float* sryL = sry + L * NQb;

    // pass A: k bits 0-3 on regs <-> qubits 11..8 (own slots)
    if (L) {
#define LDA_(j) amp[j] = samp[aB ^ OA<L, j>::v];
        REP16(LDA_)
#undef LDA_
    }
    ry4_lift<11>(amp, tpL, sryL);
#define STA_(j) samp[aB ^ OA<L, j>::v] = amp[j];
    REP16(STA_)
#undef STA_
    __syncthreads();

    // pass B: k bits 4-7 on regs <-> qubits 7..4 (own slots)
#define LDB_(j) amp[j] = samp[bB ^ OB<L, j>::v];
    REP16(LDB_)
#undef LDB_
    ry4_lift<7>(amp, tpL, sryL);
#define STB_(j) samp[bB ^ OB<L, j>::v] = amp[j];
    REP16(STB_)
#undef STB_
    __syncthreads();

    // pass C: k bits 8-11 on regs <-> qubits 3..0 (own slots)
#define LDC_(j) amp[j] = samp[cB ^ OC<L, j>::v];
    REP16(LDC_)
#undef LDC_
    ry4_lift<3>(amp, tpL, sryL);

    if (L < 4) {
        // fused RZ: phase(kC) = phb(t) + zoffC[L][j];  t bit b <-> qubit (11-b)
        const float* tzL = tz + L * NQb;
        float phb = -0.5f * Tsum[L];
        if (t & 1)   phb += tzL[11];
        if (t & 2)   phb += tzL[10];
        if (t & 4)   phb += tzL[9];
        if (t & 8)   phb += tzL[8];
        if (t & 16)  phb += tzL[7];
        if (t & 32)  phb += tzL[6];
        if (t & 64)  phb += tzL[5];
        if (t & 128) phb += tzL[4];
        const float* zoL = zoffC[L];
#pragma unroll
        for (int j = 0; j < 16; ++j) {
            float sp, cp;
            __sincosf(phb + zoL[j], &sp, &cp);
            amp[j] = cmulp(amp[j], cp, sp);
        }
        // store own slots — CNOT handled by slot-map relabel (no scatter)
#define STC_(j) samp[cB ^ OC<L, j>::v] = amp[j];
        REP16(STC_)
#undef STC_
        __syncthreads();
    } else {
        // last layer: RZ is |.|^2-invariant; fold final CNOT into weights
        u64 accp = 0ull;
#define MEA_(j) { const int tm = TAU_t ^ TJc<j>::v; \
                  const float w = (float)(NQb - 2 * __popc(tm)); \
                  accp = f2fma(f2mul(amp[j], amp[j]), pk2(w, w), accp); }
        REP16(MEA_)
#undef MEA_
        float wl, wh; unpk2(accp, wl, wh);
        accm = wl + wh;
    }
}

__global__ void __launch_bounds__(TPB, 4)
qsim_kernel(const float* __restrict__ xin, const float* __restrict__ params,
            const float* __restrict__ lin_w, const float* __restrict__ lin_b,
            float* __restrict__ out) {
    __shared__ u64 samp[SDIM];             // slot map evolves: S_L(k) = beta2(sigma^L(k))
    __shared__ u64 TLs[64], THs[64];       // layer-0 product tables
    __shared__ float2 sv[NQb][2];
    __shared__ float sry[60];              // sin(th) (lifting q), layers 1..5
    __shared__ float tP[60];               // -tan(th/2) (lifting p)
    __shared__ float tz[48];               // RZ angles, layers 1..4
    __shared__ float zoffC[4][16];         // RZ offsets for pass-C reg bits (qubits 3..0)
    __shared__ float Tsum[4];
    __shared__ float red8[8];

    const int t = threadIdx.x;             // 8 bits
    const int blk = blockIdx.x;
    const int lane = t & 31;

    // ---------- setup ----------
    if (t < NQb) {
        const float h = tanhf(xin[blk * NQb + t]) * 1.5707963267948966f;
        const float ce = cosf(h), se = sinf(h);
        const float th = 0.5f * params[t];
        const float ct = cosf(th), st = sinf(th);
        const float a = ct * ce - st * se, b = st * ce + ct * se;
        const float t0 = params[NQb + t];
        const float c0 = cosf(0.5f * t0), s0 = sinf(0.5f * t0);
        sv[t][0] = make_float2(a * c0, -a * s0);
        sv[t][1] = make_float2(b * c0,  b * s0);
    }
    if (t < 60) {
        const int L = t / NQb, q = t - L * NQb;
        const float th = 0.5f * params[(L + 1) * 24 + q];
        sry[t] = sinf(th);
        tP[t] = -tanf(0.5f * th);
    }
    if (t < 48) {
        const int L = t / NQb, q = t - L * NQb;
        tz[t] = params[(L + 1) * 24 + NQb + q];
    }
    __syncthreads();

    if (t < 128) {
        const int n = t & 63;
        const int qb = (t < 64) ? 11 : 5;
        float2 a = sv[qb][n & 1];
#pragma unroll
        for (int p = 1; p < 6; ++p) {
            const float2 w = sv[qb - p][(n >> p) & 1];
            a = make_float2(a.x * w.x - a.y * w.y, a.x * w.y + a.y * w.x);
        }
        if (t < 64) TLs[n] = pk2(a.x, a.y); else THs[n] = pk2(a.x, a.y);
    }
    if (t < 64) {   // zoffC[L][j]: pass-C reg bit bb (k bit 8+bb) <-> qubit (3-bb)
        const int L = t >> 4, j = t & 15;
        const float* tzL = tz + L * NQb;
        float zo = 0.f;
#pragma unroll
        for (int bb = 0; bb < 4; ++bb)
            if ((j >> bb) & 1) zo += tzL[3 - bb];
        zoffC[L][j] = zo;
    }
    if (t >= 128 && t < 132) {
        const int L = t - 128; float s = 0.f;
#pragma unroll
        for (int q = 0; q < NQb; ++q) s += tz[L * NQb + q];
        Tsum[L] = s;
    }
    __syncthreads();

    // ---------- per-thread evolving index bases (runtime sigma: 3 calls/layer) ----------
    int vA = t << 4;
    int vB = (t & 15) | ((t >> 4) << 8);
    int vC = t;
    const int TAU_t = tau12c(t);

    // ---------- layer-1 pass-A input: layer 0 + CNOT folded ----------
    const int S_t = sigma12c(t << 4);
    u64 amp[16];
#define INI_(j) { const int m = S_t ^ SJc<j>::v; \
                  amp[j] = cmul2(TLs[m & 63], THs[(m >> 6) & 63]); }
    REP16(INI_)
#undef INI_

    float accm = 0.f;

    layer_body<0>(amp, samp, beta2(vA), beta2(vB), beta2(vC), tP, sry, tz, zoffC, Tsum, t, TAU_t, accm);
    vA = sigma12c(vA); vB = sigma12c(vB); vC = sigma12c(vC);
    layer_body<1>(amp, samp, beta2(vA), beta2(vB), beta2(vC), tP, sry, tz, zoffC, Tsum, t, TAU_t, accm);
    vA = sigma12c(vA); vB = sigma12c(vB); vC = sigma12c(vC);
    layer_body<2>(amp, samp, beta2(vA), beta2(vB), beta2(vC), tP, sry, tz, zoffC, Tsum, t, TAU_t, accm);
    vA = sigma12c(vA); vB = sigma12c(vB); vC = sigma12c(vC);
    layer_body<3>(amp, samp, beta2(vA), beta2(vB), beta2(vC), tP, sry, tz, zoffC, Tsum, t, TAU_t, accm);
    vA = sigma12c(vA); vB = sigma12c(vB); vC = sigma12c(vC);
    layer_body<4>(amp, samp, beta2(vA), beta2(vB), beta2(vC), tP, sry, tz, zoffC, Tsum, t, TAU_t, accm);

    // ---------- reduction (8 warps) + head ----------
#pragma unroll
    for (int o = 16; o; o >>= 1) accm += __shfl_xor_sync(0xffffffffu, accm, o);
    if (lane == 0) red8[t >> 5] = accm;
    __syncthreads();
    if (t == 0) {
        float m = 0.f;
#pragma unroll
        for (int w = 0; w < 8; ++w) m += red8[w];
        const float z = (m / (float)NQb) * lin_w[0] + lin_b[0];
        out[blk] = 1.f / (1.f + expf(-z));
    }
}

extern "C" void kernel_launch(void* const* d_in, const int* in_sizes, int n_in,
                              void* d_out, int out_size) {
    const float* x      = (const float*)d_in[0];
    const float* params = (const float*)d_in[1];
    const float* lw     = (const float*)d_in[2];
    const float* lb     = (const float*)d_in[3];
    const int Bn = in_sizes[0] / NQb;      // 512
    qsim_kernel<<<Bn, TPB>>>(x, params, lw, lb, (float*)d_out);
}

// round 16
// speedup vs baseline: 4.6555x; 1.6097x over previous
#include <cuda_runtime.h>
#include <math.h>

#define NQb 12
#define SDIM 4096
#define TPB 256

typedef unsigned long long u64;

// ---------- packed f32x2 helpers ----------
__device__ __forceinline__ u64 pk2(float lo, float hi) {
    u64 r; asm("mov.b64 %0,{%1,%2};" : "=l"(r) : "f"(lo), "f"(hi)); return r;
}
__device__ __forceinline__ void unpk2(u64 v, float& lo, float& hi) {
    asm("mov.b64 {%0,%1},%2;" : "=f"(lo), "=f"(hi) : "l"(v));
}
__device__ __forceinline__ u64 f2mul(u64 a, u64 b) {
    u64 d; asm("mul.rn.f32x2 %0,%1,%2;" : "=l"(d) : "l"(a), "l"(b)); return d;
}
__device__ __forceinline__ u64 f2fma(u64 a, u64 b, u64 c) {
    u64 d; asm("fma.rn.f32x2 %0,%1,%2,%3;" : "=l"(d) : "l"(a), "l"(b), "l"(c)); return d;
}
__device__ __forceinline__ u64 cswap(u64 v) {
    float x, y; unpk2(v, x, y); return pk2(y, x);
}
__device__ __forceinline__ u64 cmulp(u64 a, float br, float bi) {   // a*(br+i bi)
    return f2fma(pk2(-bi, bi), cswap(a), f2mul(pk2(br, br), a));
}
__device__ __forceinline__ u64 cmul2(u64 a, u64 b) {
    float br, bi; unpk2(b, br, bi); return cmulp(a, br, bi);
}

// swizzle beta (R11, verified fast): conflict-free per 16-lane phase for all patterns
__device__ __forceinline__ int beta_s(int k) { return k ^ ((k >> 4) & 15); }

// CNOT-chain permutation (verified): state_after[k] = state_before[sigma(k)]
__device__ __forceinline__ int sigma12(int x) {
    x ^= (x & 1) << 11;
#pragma unroll
    for (int p = 1; p <= 11; ++p) x ^= ((x >> p) & 1) << (p - 1);
    return x;
}
// tau = sigma^{-1}
__device__ __forceinline__ int tau12(int x) {
#pragma unroll
    for (int p = 11; p >= 1; --p) x ^= ((x >> p) & 1) << (p - 1);
    x ^= (x & 1) << 11;
    return x;
}

// 4 RY rotations via lifting (3 FMA per pair): reg bit bb <-> qubit (QHI-bb).
template <int QHI>
__device__ __forceinline__ void ry4_lift(u64 a[16], const float* __restrict__ tpL,
                                         const float* __restrict__ sryL) {
#pragma unroll
    for (int bb = 0; bb < 4; ++bb) {
        const float p = tpL[QHI - bb], q = sryL[QHI - bb];
        const u64 pp = pk2(p, p), qq = pk2(q, q);
        const int m = 1 << bb;
#pragma unroll
        for (int j0 = 0; j0 < 16; ++j0) {
            if (j0 & m) continue;        // compile-time pruned
            const int j1 = j0 | m;
            a[j0] = f2fma(pp, a[j1], a[j0]);
            a[j1] = f2fma(qq, a[j0], a[j1]);
            a[j0] = f2fma(pp, a[j1], a[j0]);
        }
    }
}

__global__ void __launch_bounds__(TPB, 4)
qsim_kernel(const float* __restrict__ xin, const float* __restrict__ params,
            const float* __restrict__ lin_w, const float* __restrict__ lin_b,
            float* __restrict__ out) {
    __shared__ u64 samp[SDIM];             // packed (re,im), slot beta(k) (tau-folded post-CNOT)
    __shared__ u64 TLs[64], THs[64];       // layer-0 product tables
    __shared__ float2 sv[NQb][2];
    __shared__ float sry[60];              // sin(th) (lifting q), layers 1..5
    __shared__ float tP[60];               // -tan(th/2) (lifting p)
    __shared__ float tz[48];               // RZ angles, layers 1..4
    __shared__ float2 zw[4][4];            // unit vectors e^{i tzL[3-b]} for Gray walk
    __shared__ float Tsum[4];
    __shared__ float red8[8];

    const int t = threadIdx.x;             // 8 bits
    const int blk = blockIdx.x;
    const int lane = t & 31;

    // ---------- setup ----------
    if (t < NQb) {
        const float h = tanhf(xin[blk * NQb + t]) * 1.5707963267948966f;
        const float ce = cosf(h), se = sinf(h);
        const float th = 0.5f * params[t];
        const float ct = cosf(th), st = sinf(th);
        const float a = ct * ce - st * se, b = st * ce + ct * se;
        const float t0 = params[NQb + t];
        const float c0 = cosf(0.5f * t0), s0 = sinf(0.5f * t0);
        sv[t][0] = make_float2(a * c0, -a * s0);
        sv[t][1] = make_float2(b * c0,  b * s0);
    }
    if (t < 60) {
        const int L = t / NQb, q = t - L * NQb;
        const float th = 0.5f * params[(L + 1) * 24 + q];
        sry[t] = sinf(th);
        tP[t] = -tanf(0.5f * th);
    }
    if (t < 48) {
        const int L = t / NQb, q = t - L * NQb;
        tz[t] = params[(L + 1) * 24 + NQb + q];
    }
    __syncthreads();

    // product tables: TL over qubits 11..6 (k bits 0-5), TH over qubits 5..0 (k bits 6-11)
    if (t < 128) {
        const int n = t & 63;
        const int qb = (t < 64) ? 11 : 5;
        float2 a = sv[qb][n & 1];
#pragma unroll
        for (int p = 1; p < 6; ++p) {
            const float2 w = sv[qb - p][(n >> p) & 1];
            a = make_float2(a.x * w.x - a.y * w.y, a.x * w.y + a.y * w.x);
        }
        if (t < 64) TLs[n] = pk2(a.x, a.y); else THs[n] = pk2(a.x, a.y);
    }
    if (t < 16) {   // zw[L][b] = e^{i tzL[3-b]}  (Gray-walk factor for reg bit b)
        const int L = t >> 2, b = t & 3;
        float s, c; __sincosf(tz[L * NQb + (3 - b)], &s, &c);
        zw[L][b] = make_float2(c, s);
    }
    if (t >= 128 && t < 132) {
        const int L = t - 128; float s = 0.f;
#pragma unroll
        for (int q = 0; q < NQb; ++q) s += tz[L * NQb + q];
        Tsum[L] = s;
    }
    __syncthreads();

    // ---------- per-thread invariants (R11) ----------
    const int Abase = (t << 4) ^ (t & 15);             // beta((t<<4)|j) = Abase ^ j
    const int Bbase = (t & 15) | ((t >> 4) << 8);      // beta(kB) = Bbase ^ (j<<4) ^ j
    const int Cbase = t ^ ((t >> 4) & 15);             // beta(kC) = Cbase ^ (j<<8)
    const int PT_t  = beta_s(tau12(t));                // tau-store, t-part
    const int TAU_t = tau12(t);                        // measurement fold

    // ---------- layer-1 pass-A input: layer 0 + CNOT folded, kA=(t<<4)|j ----------
    const int S_t = sigma12(t << 4);
    u64 amp[16];
#pragma unroll
    for (int j = 0; j < 16; ++j) {
        const int m = S_t ^ sigma12(j);
        amp[j] = cmul2(TLs[m & 63], THs[(m >> 6) & 63]);
    }

    float accm = 0.f;

#pragma unroll 1
    for (int L = 0; L < 5; ++L) {          // physical layers 1..5
        const float* tpL  = tP  + L * NQb;
        const float* sryL = sry + L * NQb;

        // pass A: k bits 0-3 on regs <-> qubits 11..8 (in-place per-thread)
        if (L) {
#pragma unroll
            for (int j = 0; j < 16; ++j) amp[j] = samp[Abase ^ j];
        }
        ry4_lift<11>(amp, tpL, sryL);
#pragma unroll
        for (int j = 0; j < 16; ++j) samp[Abase ^ j] = amp[j];
        __syncthreads();

        // pass B: k bits 4-7 on regs <-> qubits 7..4 (in-place per-thread)
#pragma unroll
        for (int j = 0; j < 16; ++j) amp[j] = samp[Bbase ^ ((j << 4) ^ j)];
        ry4_lift<7>(amp, tpL, sryL);
#pragma unroll
        for (int j = 0; j < 16; ++j) samp[Bbase ^ ((j << 4) ^ j)] = amp[j];
        __syncthreads();

        // pass C: k bits 8-11 on regs <-> qubits 3..0
#pragma unroll
        for (int j = 0; j < 16; ++j) amp[j] = samp[Cbase ^ (j << 8)];
        ry4_lift<3>(amp, tpL, sryL);

        if (L < 4) {
            // fused RZ, Gray-code tree: E_j = e^{i(phb + zoff(j))}, 1 sincos + 15 cmuls
            const float* tzL = tz + L * NQb;
            float phb = -0.5f * Tsum[L];
            if (t & 1)   phb += tzL[11];
            if (t & 2)   phb += tzL[10];
            if (t & 4)   phb += tzL[9];
            if (t & 8)   phb += tzL[8];
            if (t & 16)  phb += tzL[7];
            if (t & 32)  phb += tzL[6];
            if (t & 64)  phb += tzL[5];
            if (t & 128) phb += tzL[4];
            const float2 w0 = zw[L][0], w1 = zw[L][1], w2 = zw[L][2], w3 = zw[L][3];
            float ex, ey; __sincosf(phb, &ey, &ex);   // ex=cos, ey=sin
            amp[0] = cmulp(amp[0], ex, ey);
#define STEPP(g, wv) { const float nx = ex*wv.x - ey*wv.y, ny = ex*wv.y + ey*wv.x; \
                       ex = nx; ey = ny; amp[g] = cmulp(amp[g], ex, ey); }
#define STEPM(g, wv) { const float nx = ex*wv.x + ey*wv.y, ny = ey*wv.x - ex*wv.y; \
                       ex = nx; ey = ny; amp[g] = cmulp(amp[g], ex, ey); }
            STEPP(1,  w0) STEPP(3,  w1) STEPM(2,  w0) STEPP(6,  w2)
            STEPP(7,  w0) STEPM(5,  w1) STEPM(4,  w0) STEPP(12, w3)
            STEPP(13, w0) STEPP(15, w1) STEPM(14, w0) STEPM(10, w2)
            STEPP(11, w0) STEPM(9,  w1) STEPM(8,  w0)
#undef STEPP
#undef STEPM
            __syncthreads();   // all pass-C loads consumed before permuted overwrite
            // CNOT fold: amp(kC) -> slot beta(tau(kC))
#pragma unroll
            for (int j = 0; j < 16; ++j)
                samp[PT_t ^ beta_s(tau12(j << 8))] = amp[j];
            __syncthreads();
        } else {
            // last layer: RZ is |.|^2-invariant; fold final CNOT into weights
            u64 accp = 0ull;
#pragma unroll
            for (int j = 0; j < 16; ++j) {
                const int tm = TAU_t ^ tau12(j << 8);
                const float w = (float)(NQb - 2 * __popc(tm));
                accp = f2fma(f2mul(amp[j], amp[j]), pk2(w, w), accp);
            }
            float wl, wh; unpk2(accp, wl, wh);
            accm = wl + wh;
        }
    }

    // ---------- reduction (8 warps) + head ----------
#pragma unroll
    for (int o = 16; o; o >>= 1) accm += __shfl_xor_sync(0xffffffffu, accm, o);
    if (lane == 0) red8[t >> 5] = accm;
    __syncthreads();
    if (t == 0) {
        float m = 0.f;
#pragma unroll
        for (int w = 0; w < 8; ++w) m += red8[w];
        const float z = (m / (float)NQb) * lin_w[0] + lin_b[0];
        out[blk] = 1.f / (1.f + expf(-z));
    }
}

extern "C" void kernel_launch(void* const* d_in, const int* in_sizes, int n_in,
                              void* d_out, int out_size) {
    const float* x      = (const float*)d_in[0];
    const float* params = (const float*)d_in[1];
    const float* lw     = (const float*)d_in[2];
    const float* lb     = (const float*)d_in[3];
    const int Bn = in_sizes[0] / NQb;      // 512
    qsim_kernel<<<Bn, TPB>>>(x, params, lw, lb, (float*)d_out);
}

// round 17
// speedup vs baseline: 4.7140x; 1.0126x over previous
#include <cuda_runtime.h>
#include <math.h>

#define NQb 12
#define SDIM 4096
#define TPB 256
#define SMEM_DYN (2 * SDIM * 8)

typedef unsigned long long u64;

// ---------- packed f32x2 helpers ----------
__device__ __forceinline__ u64 pk2(float lo, float hi) {
    u64 r; asm("mov.b64 %0,{%1,%2};" : "=l"(r) : "f"(lo), "f"(hi)); return r;
}
__device__ __forceinline__ void unpk2(u64 v, float& lo, float& hi) {
    asm("mov.b64 {%0,%1},%2;" : "=f"(lo), "=f"(hi) : "l"(v));
}
__device__ __forceinline__ u64 f2mul(u64 a, u64 b) {
    u64 d; asm("mul.rn.f32x2 %0,%1,%2;" : "=l"(d) : "l"(a), "l"(b)); return d;
}
__device__ __forceinline__ u64 f2fma(u64 a, u64 b, u64 c) {
    u64 d; asm("fma.rn.f32x2 %0,%1,%2,%3;" : "=l"(d) : "l"(a), "l"(b), "l"(c)); return d;
}
__device__ __forceinline__ u64 cswap(u64 v) {
    float x, y; unpk2(v, x, y); return pk2(y, x);
}
__device__ __forceinline__ u64 cmulp(u64 a, float br, float bi) {   // a*(br+i bi)
    return f2fma(pk2(-bi, bi), cswap(a), f2mul(pk2(br, br), a));
}
__device__ __forceinline__ u64 cmul2(u64 a, u64 b) {
    float br, bi; unpk2(b, br, bi); return cmulp(a, br, bi);
}

// swizzle beta (verified fast): conflict-free per 16-lane phase for all patterns
__device__ __forceinline__ int beta_s(int k) { return k ^ ((k >> 4) & 15); }

// CNOT-chain permutation (verified): state_after[k] = state_before[sigma(k)]
__device__ __forceinline__ int sigma12(int x) {
    x ^= (x & 1) << 11;
#pragma unroll
    for (int p = 1; p <= 11; ++p) x ^= ((x >> p) & 1) << (p - 1);
    return x;
}
// tau = sigma^{-1}
__device__ __forceinline__ int tau12(int x) {
#pragma unroll
    for (int p = 11; p >= 1; --p) x ^= ((x >> p) & 1) << (p - 1);
    x ^= (x & 1) << 11;
    return x;
}

// 4 RY rotations via lifting, applied to TWO register sets (independent ILP).
template <int QHI>
__device__ __forceinline__ void ry4_lift2(u64 a[16], u64 b[16],
                                          const float* __restrict__ tpL,
                                          const float* __restrict__ sryL) {
#pragma unroll
    for (int bb = 0; bb < 4; ++bb) {
        const float p = tpL[QHI - bb], q = sryL[QHI - bb];
        const u64 pp = pk2(p, p), qq = pk2(q, q);
        const int m = 1 << bb;
#pragma unroll
        for (int j0 = 0; j0 < 16; ++j0) {
            if (j0 & m) continue;        // compile-time pruned
            const int j1 = j0 | m;
            a[j0] = f2fma(pp, a[j1], a[j0]);
            b[j0] = f2fma(pp, b[j1], b[j0]);
            a[j1] = f2fma(qq, a[j0], a[j1]);
            b[j1] = f2fma(qq, b[j0], b[j1]);
            a[j0] = f2fma(pp, a[j1], a[j0]);
            b[j0] = f2fma(pp, b[j1], b[j0]);
        }
    }
}

__global__ void __launch_bounds__(TPB, 2)
qsim_kernel(const float* __restrict__ xin, const float* __restrict__ params,
            const float* __restrict__ lin_w, const float* __restrict__ lin_b,
            float* __restrict__ out) {
    extern __shared__ u64 dysm[];          // sampA[SDIM] | sampB[SDIM]
    u64* __restrict__ sampA = dysm;
    u64* __restrict__ sampB = dysm + SDIM;

    __shared__ u64 TLs[2][64], THs[2][64]; // layer-0 product tables per element
    __shared__ float2 sv[2][NQb][2];
    __shared__ float sry[60];              // sin(th) (lifting q), layers 1..5
    __shared__ float tP[60];               // -tan(th/2) (lifting p)
    __shared__ float tz[48];               // RZ angles, layers 1..4
    __shared__ float2 zw[4][4];            // Gray-walk unit factors e^{i tzL[3-b]}
    __shared__ float Tsum[4];
    __shared__ float red8[2][8];

    const int t = threadIdx.x;             // 8 bits
    const int blk = blockIdx.x;            // handles batch elements 2*blk, 2*blk+1
    const int lane = t & 31;

    // ---------- setup phase 1 ----------
    if (t < 24) {                          // per-element encoding+layer0 2-vectors
        const int e = t >= NQb, q = t - e * NQb;
        const float h = tanhf(xin[(blk * 2 + e) * NQb + q]) * 1.5707963267948966f;
        const float ce = cosf(h), se = sinf(h);
        const float th = 0.5f * params[q];
        const float ct = cosf(th), st = sinf(th);
        const float a = ct * ce - st * se, b = st * ce + ct * se;
        const float t0 = params[NQb + q];
        const float c0 = cosf(0.5f * t0), s0 = sinf(0.5f * t0);
        sv[e][q][0] = make_float2(a * c0, -a * s0);
        sv[e][q][1] = make_float2(b * c0,  b * s0);
    }
    if (t >= 64 && t < 124) {
        const int i = t - 64;
        const int L = i / NQb, q = i - L * NQb;
        const float th = 0.5f * params[(L + 1) * 24 + q];
        sry[i] = sinf(th);
        tP[i] = -tanf(0.5f * th);
    }
    if (t >= 128 && t < 176) {
        const int i = t - 128;
        const int L = i / NQb, q = i - L * NQb;
        tz[i] = params[(L + 1) * 24 + NQb + q];
    }
    __syncthreads();

    // ---------- setup phase 2: product tables (both elements), zw, Tsum ----------
    {
        const int e = t >> 7, n = t & 63;
        const int qb = (t & 64) ? 5 : 11;  // TL over qubits 11..6 (bits 0-5), TH 5..0
        float2 a = sv[e][qb][n & 1];
#pragma unroll
        for (int p = 1; p < 6; ++p) {
            const float2 w = sv[e][qb - p][(n >> p) & 1];
            a = make_float2(a.x * w.x - a.y * w.y, a.x * w.y + a.y * w.x);
        }
        if (t & 64) THs[e][n] = pk2(a.x, a.y); else TLs[e][n] = pk2(a.x, a.y);
    }
    if (t < 16) {   // zw[L][b] = e^{i tzL[3-b]}
        const int L = t >> 2, b = t & 3;
        float s, c; __sincosf(tz[L * NQb + (3 - b)], &s, &c);
        zw[L][b] = make_float2(c, s);
    }
    if (t >= 16 && t < 20) {
        const int L = t - 16; float s = 0.f;
#pragma unroll
        for (int q = 0; q < NQb; ++q) s += tz[L * NQb + q];
        Tsum[L] = s;
    }
    __syncthreads();

    // ---------- per-thread invariants ----------
    const int Abase = (t << 4) ^ (t & 15);             // beta((t<<4)|j) = Abase ^ j
    const int Bbase = (t & 15) | ((t >> 4) << 8);      // beta(kB) = Bbase ^ (j<<4) ^ j
    const int Cbase = t ^ ((t >> 4) & 15);             // beta(kC) = Cbase ^ (j<<8)
    const int PT_t  = beta_s(tau12(t));                // tau-store, t-part
    const int TAU_t = tau12(t);                        // measurement fold

    // ---------- layer-1 pass-A input: layer 0 + CNOT folded, kA=(t<<4)|j ----------
    const int S_t = sigma12(t << 4);
    u64 ampA[16], ampB[16];
#pragma unroll
    for (int j = 0; j < 16; ++j) {
        const int m = S_t ^ sigma12(j);
        ampA[j] = cmul2(TLs[0][m & 63], THs[0][(m >> 6) & 63]);
        ampB[j] = cmul2(TLs[1][m & 63], THs[1][(m >> 6) & 63]);
    }

    float accA = 0.f, accB = 0.f;

#pragma unroll 1
    for (int L = 0; L < 5; ++L) {          // physical layers 1..5
        const float* tpL  = tP  + L * NQb;
        const float* sryL = sry + L * NQb;

        // pass A: k bits 0-3 on regs <-> qubits 11..8 (in-place per-thread)
        if (L) {
#pragma unroll
            for (int j = 0; j < 16; ++j) ampA[j] = sampA[Abase ^ j];
#pragma unroll
            for (int j = 0; j < 16; ++j) ampB[j] = sampB[Abase ^ j];
        }
        ry4_lift2<11>(ampA, ampB, tpL, sryL);
#pragma unroll
        for (int j = 0; j < 16; ++j) sampA[Abase ^ j] = ampA[j];
#pragma unroll
        for (int j = 0; j < 16; ++j) sampB[Abase ^ j] = ampB[j];
        __syncthreads();

        // pass B: k bits 4-7 on regs <-> qubits 7..4 (in-place per-thread)
#pragma unroll
        for (int j = 0; j < 16; ++j) ampA[j] = sampA[Bbase ^ ((j << 4) ^ j)];
#pragma unroll
        for (int j = 0; j < 16; ++j) ampB[j] = sampB[Bbase ^ ((j << 4) ^ j)];
        ry4_lift2<7>(ampA, ampB, tpL, sryL);
#pragma unroll
        for (int j = 0; j < 16; ++j) sampA[Bbase ^ ((j << 4) ^ j)] = ampA[j];
#pragma unroll
        for (int j = 0; j < 16; ++j) sampB[Bbase ^ ((j << 4) ^ j)] = ampB[j];
        __syncthreads();

        // pass C: k bits 8-11 on regs <-> qubits 3..0
#pragma unroll
        for (int j = 0; j < 16; ++j) ampA[j] = sampA[Cbase ^ (j << 8)];
#pragma unroll
        for (int j = 0; j < 16; ++j) ampB[j] = sampB[Cbase ^ (j << 8)];
        ry4_lift2<3>(ampA, ampB, tpL, sryL);

        if (L < 4) {
            // fused RZ, Gray-code walk: 1 sincos + 15 scalar complex steps (2 chains)
            const float* tzL = tz + L * NQb;
            float phb = -0.5f * Tsum[L];
            if (t & 1)   phb += tzL[11];
            if (t & 2)   phb += tzL[10];
            if (t & 4)   phb += tzL[9];
            if (t & 8)   phb += tzL[8];
            if (t & 16)  phb += tzL[7];
            if (t & 32)  phb += tzL[6];
            if (t & 64)  phb += tzL[5];
            if (t & 128) phb += tzL[4];
            const float2 w0 = zw[L][0], w1 = zw[L][1], w2 = zw[L][2], w3 = zw[L][3];
            float ex, ey; __sincosf(phb, &ey, &ex);   // ex=cos, ey=sin
            ampA[0] = cmulp(ampA[0], ex, ey);
            ampB[0] = cmulp(ampB[0], ex, ey);
#define STEPP(g, wv) { const float nx = ex*wv.x - ey*wv.y, ny = ex*wv.y + ey*wv.x; \
                       ex = nx; ey = ny; ampA[g] = cmulp(ampA[g], ex, ey); \
                       ampB[g] = cmulp(ampB[g], ex, ey); }
#define STEPM(g, wv) { const float nx = ex*wv.x + ey*wv.y, ny = ey*wv.x - ex*wv.y; \
                       ex = nx; ey = ny; ampA[g] = cmulp(ampA[g], ex, ey); \
                       ampB[g] = cmulp(ampB[g], ex, ey); }
            STEPP(1,  w0) STEPP(3,  w1) STEPM(2,  w0) STEPP(6,  w2)
            STEPP(7,  w0) STEPM(5,  w1) STEPM(4,  w0) STEPP(12, w3)
            STEPP(13, w0) STEPP(15, w1) STEPM(14, w0) STEPM(10, w2)
            STEPP(11, w0) STEPM(9,  w1) STEPM(8,  w0)
#undef STEPP
#undef STEPM
            __syncthreads();   // all pass-C loads consumed before permuted overwrite
            // CNOT fold: amp(kC) -> slot beta(tau(kC))
#pragma unroll
            for (int j = 0; j < 16; ++j)
                sampA[PT_t ^ beta_s(tau12(j << 8))] = ampA[j];
#pragma unroll
            for (int j = 0; j < 16; ++j)
                sampB[PT_t ^ beta_s(tau12(j << 8))] = ampB[j];
            __syncthreads();
        } else {
            // last layer: RZ is |.|^2-invariant; fold final CNOT into weights
            u64 apA = 0ull, apB = 0ull;
#pragma unroll
            for (int j = 0; j < 16; ++j) {
                const int tm = TAU_t ^ tau12(j << 8);
                const float w = (float)(NQb - 2 * __popc(tm));
                const u64 ww = pk2(w, w);
                apA = f2fma(f2mul(ampA[j], ampA[j]), ww, apA);
                apB = f2fma(f2mul(ampB[j], ampB[j]), ww, apB);
            }
            float l0, h0; unpk2(apA, l0, h0); accA = l0 + h0;
            float l1, h1; unpk2(apB, l1, h1); accB = l1 + h1;
        }
    }

    // ---------- reduction (8 warps, 2 elements) + head ----------
#pragma unroll
    for (int o = 16; o; o >>= 1) {
        accA += __shfl_xor_sync(0xffffffffu, accA, o);
        accB += __shfl_xor_sync(0xffffffffu, accB, o);
    }
    if (lane == 0) { red8[0][t >> 5] = accA; red8[1][t >> 5] = accB; }
    __syncthreads();
    if (t < 2) {
        float m = 0.f;
#pragma unroll
        for (int w = 0; w < 8; ++w) m += red8[t][w];
        const float z = (m / (float)NQb) * lin_w[0] + lin_b[0];
        out[blk * 2 + t] = 1.f / (1.f + expf(-z));
    }
}

extern "C" void kernel_launch(void* const* d_in, const int* in_sizes, int n_in,
                              void* d_out, int out_size) {
    const float* x      = (const float*)d_in[0];
    const float* params = (const float*)d_in[1];
    const float* lw     = (const float*)d_in[2];
    const float* lb     = (const float*)d_in[3];
    const int Bn = in_sizes[0] / NQb;      // 512
    cudaFuncSetAttribute(qsim_kernel, cudaFuncAttributeMaxDynamicSharedMemorySize,
                         SMEM_DYN);
    qsim_kernel<<<Bn / 2, TPB, SMEM_DYN>>>(x, params, lw, lb, (float*)d_out);
}